// round 6
// baseline (speedup 1.0000x reference)
#include <cuda_runtime.h>
#include <cstdint>

// ---------------------------------------------------------------------------
// Problem constants
// ---------------------------------------------------------------------------
#define FEAT_DIM   512
#define EMBED_DIM  256
#define BATCH      16384
#define NUM_SAMPLE 10
#define RRELU_SLOPE (11.0f / 48.0f)

// Fixed-point scales: w ~ w1*2^-10 + w2*2^-17 ; a ~ a1*2^-6 + a2*2^-13
#define S_MAIN  1.52587890625e-5f      // 2^-16
#define S_CROSS 1.1920928955078125e-7f // 2^-23

// Fused-kernel tiling: CTA = 256(M) x 32(N batch rows), k-chunks of 32
#define BN 32
#define BKB 32
#define NCH (FEAT_DIM / BKB)       // 16
#define ROWB_A 48                  // 32 data + 16 pad  (conflict-free ldmatrix)
#define ROWB_B 528                 // 512 data + 16 pad (conflict-free ldmatrix)
#define SB1 0
#define SB2 (BN * ROWB_B)          // 16896
#define SA0 (2 * BN * ROWB_B)      // 33792
#define A_LIMB (EMBED_DIM * ROWB_A)    // 12288
#define A_STAGE (2 * A_LIMB)           // 24576 (limb1 + limb2)
#define SMEM_TOTAL (SA0 + 2 * A_STAGE) // 82944 -> 2 CTAs/SM

// ---------------------------------------------------------------------------
// Scratch (device globals: allocation-free rule)
// ---------------------------------------------------------------------------
__device__ int8_t g_w1[(size_t)EMBED_DIM * FEAT_DIM];  // weight limb 1
__device__ int8_t g_w2[(size_t)EMBED_DIM * FEAT_DIM];  // weight limb 2

// ---------------------------------------------------------------------------
// PTX helpers (sm_80-era; valid on compute_100 baseline target)
// ---------------------------------------------------------------------------
__device__ __forceinline__ uint32_t smem_to_u32(const void* p) {
    uint32_t a;
    asm("{ .reg .u64 t; cvta.to.shared.u64 t, %1; cvt.u32.u64 %0, t; }" : "=r"(a) : "l"(p));
    return a;
}

#define CP_ASYNC16(saddr, gptr) \
    asm volatile("cp.async.cg.shared.global [%0], [%1], 16;" :: "r"(saddr), "l"(gptr))
#define CP_COMMIT() asm volatile("cp.async.commit_group;")
#define CP_WAIT1()  asm volatile("cp.async.wait_group 1;")
#define CP_WAIT0()  asm volatile("cp.async.wait_group 0;")

#define LDSM4(r, addr)                                                           \
    asm volatile("ldmatrix.sync.aligned.m8n8.x4.shared.b16 {%0,%1,%2,%3}, [%4];" \
                 : "=r"((r)[0]), "=r"((r)[1]), "=r"((r)[2]), "=r"((r)[3])        \
                 : "r"(addr))
#define LDSM2(r, addr)                                                           \
    asm volatile("ldmatrix.sync.aligned.m8n8.x2.shared.b16 {%0,%1}, [%2];"       \
                 : "=r"((r)[0]), "=r"((r)[1])                                    \
                 : "r"(addr))

#define MMA_S8(d, a, b0_, b1_)                                                  \
    asm volatile("mma.sync.aligned.m16n8k32.row.col.s32.s8.s8.s32 "             \
                 "{%0,%1,%2,%3}, {%4,%5,%6,%7}, {%8,%9}, {%0,%1,%2,%3};"        \
                 : "+r"((d)[0]), "+r"((d)[1]), "+r"((d)[2]), "+r"((d)[3])       \
                 : "r"((a)[0]), "r"((a)[1]), "r"((a)[2]), "r"((a)[3]),          \
                   "r"(b0_), "r"(b1_))

__device__ __forceinline__ void split2(float x, float s1, float s2, int& l1, int& l2) {
    float xs = x * s1;
    xs = fminf(fmaxf(xs, -127.f), 127.f);
    const int q1 = __float2int_rn(xs);
    float r = (xs - (float)q1) * s2;
    r = fminf(fmaxf(r, -127.f), 127.f);
    l1 = q1;
    l2 = __float2int_rn(r);
}
__device__ __forceinline__ uint32_t pack4(int a, int b, int c, int d) {
    return (uint32_t)(uint8_t)a | ((uint32_t)(uint8_t)b << 8) |
           ((uint32_t)(uint8_t)c << 16) | ((uint32_t)(uint8_t)d << 24);
}

// ---------------------------------------------------------------------------
// Kernel 1: weight limbs (w*1024 -> l1 (|.|<=91); residual*128 -> l2)
// ---------------------------------------------------------------------------
__global__ void weight_split_kernel(const float* __restrict__ w) {
    const int i4 = (blockIdx.x * blockDim.x + threadIdx.x) * 4;
    const float4 v = *reinterpret_cast<const float4*>(w + i4);
    float x[4] = {v.x, v.y, v.z, v.w};
    int l1[4], l2[4];
#pragma unroll
    for (int j = 0; j < 4; ++j) split2(x[j], 1024.f, 128.f, l1[j], l2[j]);
    reinterpret_cast<uint32_t*>(g_w1)[i4 >> 2] = pack4(l1[0], l1[1], l1[2], l1[3]);
    reinterpret_cast<uint32_t*>(g_w2)[i4 >> 2] = pack4(l2[0], l2[1], l2[2], l2[3]);
}

// ---------------------------------------------------------------------------
// Kernel 2 (fused): gather+mean+quantize 32 agg rows into smem, then
// C[256,32] = 2^-16*W1A1 + 2^-23*(W1A2+W2A1) with mma.s8, fused leaky ReLU.
// 256 threads (8 warps: 4 m-warps x 2 n-warps, warp tile 64m x 16n), occ 2.
// W limbs stream through a 2-stage cp.async pipeline (issued before gather,
// so the first chunks land while the gather runs).
// ---------------------------------------------------------------------------
__global__ __launch_bounds__(256, 2) void fused_gather_gemm_kernel(
    const float* __restrict__ feat, const int* __restrict__ neigh,
    float* __restrict__ out) {
    extern __shared__ char smem[];
    const uint32_t sbase = smem_to_u32(smem);
    const int t    = threadIdx.x;
    const int lane = t & 31;
    const int w    = t >> 5;
    const int wm   = w & 3;    // m warp (x64)
    const int wn   = w >> 2;   // n warp (x16)
    const int b0   = blockIdx.x * BN;

    // --- cp.async assignment for W chunks: 1024 16B-chunks/stage, 4/thread ---
    uint32_t a_soff[4];
    const char* a_gptr[4];
#pragma unroll
    for (int j = 0; j < 4; ++j) {
        const int i    = t + j * 256;      // 0..1023
        const int limb = i >> 9;           // 0: w1, 1: w2
        const int idx  = i & 511;
        const int row  = idx >> 1;         // 0..255
        const int c    = idx & 1;          // 16B half of the 32B chunk row
        a_soff[j] = SA0 + limb * A_LIMB + row * ROWB_A + c * 16;
        a_gptr[j] = (const char*)((limb ? g_w2 : g_w1) + (size_t)row * FEAT_DIM + c * 16);
    }

    // Prologue: stage k-chunks 0 and 1 (overlap with the gather below)
#pragma unroll
    for (int ch = 0; ch < 2; ++ch) {
        const uint32_t st = ch * A_STAGE;
#pragma unroll
        for (int j = 0; j < 4; ++j) CP_ASYNC16(sbase + a_soff[j] + st, a_gptr[j] + ch * BKB);
        CP_COMMIT();
    }

    // --- gather + mean + limb-quantize into resident smem B tiles ---
    {
        const int r  = t >> 3;        // agg row 0..31
        const int kq = t & 7;         // k-sixteenth within 128-float stripe
        const int* nrow = neigh + (size_t)(b0 + r) * NUM_SAMPLE;
        int ids[NUM_SAMPLE];
#pragma unroll
        for (int s = 0; s < NUM_SAMPLE; ++s) ids[s] = nrow[s];

#pragma unroll
        for (int j = 0; j < 4; ++j) {
            const int k0 = j * 128 + kq * 16;   // this thread's 16 floats
            float acc[16];
#pragma unroll
            for (int q = 0; q < 16; ++q) acc[q] = 0.f;
#pragma unroll
            for (int s = 0; s < NUM_SAMPLE; ++s) {
                const float4* p = reinterpret_cast<const float4*>(
                    feat + (size_t)ids[s] * FEAT_DIM + k0);
#pragma unroll
                for (int q = 0; q < 4; ++q) {
                    const float4 v = p[q];
                    acc[4 * q + 0] += v.x; acc[4 * q + 1] += v.y;
                    acc[4 * q + 2] += v.z; acc[4 * q + 3] += v.w;
                }
            }
            uint32_t p1[4], p2[4];
#pragma unroll
            for (int q = 0; q < 4; ++q) {
                int l1[4], l2[4];
#pragma unroll
                for (int e = 0; e < 4; ++e)
                    split2(acc[4 * q + e] * 0.1f, 64.f, 128.f, l1[e], l2[e]);
                p1[q] = pack4(l1[0], l1[1], l1[2], l1[3]);
                p2[q] = pack4(l2[0], l2[1], l2[2], l2[3]);
            }
            const uint32_t boff = r * ROWB_B + k0;
            *reinterpret_cast<uint4*>(smem + SB1 + boff) = make_uint4(p1[0], p1[1], p1[2], p1[3]);
            *reinterpret_cast<uint4*>(smem + SB2 + boff) = make_uint4(p2[0], p2[1], p2[2], p2[3]);
        }
    }
    __syncthreads();

    // --- ldmatrix lane offsets ---
    const int sel = lane >> 3, li = lane & 7;
    const uint32_t a_base = (uint32_t)(wm * 64 + li + (sel & 1) * 8) * ROWB_A + (sel >> 1) * 16;
    const uint32_t b_base = (uint32_t)(wn * 16 + li) * ROWB_B + (sel & 1) * 16;

    int acc1[4][2][4], accX[4][2][4];
#pragma unroll
    for (int mt = 0; mt < 4; ++mt)
#pragma unroll
        for (int nt = 0; nt < 2; ++nt)
#pragma unroll
            for (int q = 0; q < 4; ++q) { acc1[mt][nt][q] = 0; accX[mt][nt][q] = 0; }

    // --- main k loop: 16 chunks of k=32 ---
    for (int ch = 0; ch < NCH; ++ch) {
        if (ch < NCH - 1) { CP_WAIT1(); } else { CP_WAIT0(); }
        __syncthreads();

        const uint32_t sA1 = sbase + SA0 + (ch & 1) * A_STAGE;
        const uint32_t sA2 = sA1 + A_LIMB;

        // B fragments for this chunk (resident tile, per n-tile per limb)
        uint32_t b1f[2][2], b2f[2][2];
#pragma unroll
        for (int nt = 0; nt < 2; ++nt) {
            const uint32_t ba = sbase + b_base + nt * (8 * ROWB_B) + ch * BKB;
            LDSM2(b1f[nt], SB1 + ba);
            LDSM2(b2f[nt], SB2 + ba);
        }
#pragma unroll
        for (int mt = 0; mt < 4; ++mt) {
            uint32_t a1f[4], a2f[4];
            const uint32_t aa = a_base + mt * (16 * ROWB_A);
            LDSM4(a1f, sA1 + aa);
            LDSM4(a2f, sA2 + aa);
#pragma unroll
            for (int nt = 0; nt < 2; ++nt) {
                MMA_S8(acc1[mt][nt], a1f, b1f[nt][0], b1f[nt][1]);
                MMA_S8(accX[mt][nt], a1f, b2f[nt][0], b2f[nt][1]);
                MMA_S8(accX[mt][nt], a2f, b1f[nt][0], b1f[nt][1]);
            }
        }
        __syncthreads();

        if (ch + 2 < NCH) {
            const uint32_t st = (ch & 1) * A_STAGE;
#pragma unroll
            for (int j = 0; j < 4; ++j)
                CP_ASYNC16(sbase + a_soff[j] + st, a_gptr[j] + (ch + 2) * BKB);
        }
        CP_COMMIT();
    }

    // --- epilogue: combine limbs, leaky ReLU, store ---
    const int lr = lane >> 2;
    const int lc = (lane & 3) * 2;
#pragma unroll
    for (int mt = 0; mt < 4; ++mt) {
#pragma unroll
        for (int nt = 0; nt < 2; ++nt) {
            float v[4];
#pragma unroll
            for (int q = 0; q < 4; ++q) {
                v[q] = __int2float_rn(acc1[mt][nt][q]) * S_MAIN +
                       __int2float_rn(accX[mt][nt][q]) * S_CROSS;
                v[q] = (v[q] >= 0.f) ? v[q] : v[q] * RRELU_SLOPE;
            }
            const int m   = wm * 64 + mt * 16 + lr;
            const int col = b0 + wn * 16 + nt * 8 + lc;
            *reinterpret_cast<float2*>(out + (size_t)m * BATCH + col) = make_float2(v[0], v[1]);
            *reinterpret_cast<float2*>(out + (size_t)(m + 8) * BATCH + col) = make_float2(v[2], v[3]);
        }
    }
}

// ---------------------------------------------------------------------------
// Launch
// ---------------------------------------------------------------------------
extern "C" void kernel_launch(void* const* d_in, const int* in_sizes, int n_in,
                              void* d_out, int out_size) {
    const float* feat  = (const float*)d_in[0];
    const float* w     = (const float*)d_in[1];
    const int*   neigh = (const int*)d_in[2];
    float*       out   = (float*)d_out;

    cudaFuncSetAttribute(fused_gather_gemm_kernel,
                         cudaFuncAttributeMaxDynamicSharedMemorySize, SMEM_TOTAL);

    weight_split_kernel<<<(EMBED_DIM * FEAT_DIM) / 4 / 256, 256>>>(w);
    fused_gather_gemm_kernel<<<BATCH / BN, 256, SMEM_TOTAL>>>(feat, neigh, out);
}

// round 7
// speedup vs baseline: 1.1433x; 1.1433x over previous
#include <cuda_runtime.h>
#include <cstdint>

// ---------------------------------------------------------------------------
// Problem constants
// ---------------------------------------------------------------------------
#define FEAT_DIM   512
#define EMBED_DIM  256
#define BATCH      16384
#define NUM_SAMPLE 10
#define RRELU_SLOPE (11.0f / 48.0f)

// Fixed-point scales: w ~ w1*2^-10 + w2*2^-17 ; a ~ a1*2^-6 + a2*2^-13
#define S_MAIN  1.52587890625e-5f      // 2^-16
#define S_CROSS 1.1920928955078125e-7f // 2^-23

// Pipeline chunking
#define NCHUNKS_PIPE 4
#define BCHUNK (BATCH / NCHUNKS_PIPE)  // 4096

// GEMM tiling (identical to round-5 winner)
#define BM 128
#define BN 64
#define BKB 64                   // k int8 per chunk
#define NCHUNK (FEAT_DIM / BKB)  // 8
#define ROWB 80                  // 64 data bytes + 16 pad (conflict-free ldmatrix)
#define TILE_W (128 * ROWB)      // 10240
#define TILE_A (64 * ROWB)       // 5120
#define STAGE_B (2 * TILE_W + 2 * TILE_A)  // 30720
#define SMEM_TOTAL (2 * STAGE_B)           // 61440, 2-stage

// ---------------------------------------------------------------------------
// Scratch (device globals: allocation-free rule)
// ---------------------------------------------------------------------------
__device__ int8_t g_a1[(size_t)BATCH * FEAT_DIM];      // agg limb 1
__device__ int8_t g_a2[(size_t)BATCH * FEAT_DIM];      // agg limb 2
__device__ int8_t g_w1[(size_t)EMBED_DIM * FEAT_DIM];  // weight limb 1
__device__ int8_t g_w2[(size_t)EMBED_DIM * FEAT_DIM];  // weight limb 2

// ---------------------------------------------------------------------------
// PTX helpers (sm_80-era; valid on compute_100 baseline target)
// ---------------------------------------------------------------------------
__device__ __forceinline__ uint32_t smem_to_u32(const void* p) {
    uint32_t a;
    asm("{ .reg .u64 t; cvta.to.shared.u64 t, %1; cvt.u32.u64 %0, t; }" : "=r"(a) : "l"(p));
    return a;
}

#define CP_ASYNC16(saddr, gptr) \
    asm volatile("cp.async.cg.shared.global [%0], [%1], 16;" :: "r"(saddr), "l"(gptr))
#define CP_COMMIT() asm volatile("cp.async.commit_group;")
#define CP_WAIT1()  asm volatile("cp.async.wait_group 1;")
#define CP_WAIT0()  asm volatile("cp.async.wait_group 0;")

#define LDSM4(r, addr)                                                           \
    asm volatile("ldmatrix.sync.aligned.m8n8.x4.shared.b16 {%0,%1,%2,%3}, [%4];" \
                 : "=r"((r)[0]), "=r"((r)[1]), "=r"((r)[2]), "=r"((r)[3])        \
                 : "r"(addr))
#define LDSM2(r, addr)                                                           \
    asm volatile("ldmatrix.sync.aligned.m8n8.x2.shared.b16 {%0,%1}, [%2];"       \
                 : "=r"((r)[0]), "=r"((r)[1])                                    \
                 : "r"(addr))

#define MMA_S8(d, a, b0_, b1_)                                                  \
    asm volatile("mma.sync.aligned.m16n8k32.row.col.s32.s8.s8.s32 "             \
                 "{%0,%1,%2,%3}, {%4,%5,%6,%7}, {%8,%9}, {%0,%1,%2,%3};"        \
                 : "+r"((d)[0]), "+r"((d)[1]), "+r"((d)[2]), "+r"((d)[3])       \
                 : "r"((a)[0]), "r"((a)[1]), "r"((a)[2]), "r"((a)[3]),          \
                   "r"(b0_), "r"(b1_))

__device__ __forceinline__ void split2(float x, float s1, float s2, int& l1, int& l2) {
    float xs = x * s1;
    xs = fminf(fmaxf(xs, -127.f), 127.f);
    const int q1 = __float2int_rn(xs);
    float r = (xs - (float)q1) * s2;
    r = fminf(fmaxf(r, -127.f), 127.f);
    l1 = q1;
    l2 = __float2int_rn(r);
}
__device__ __forceinline__ uint32_t pack4(int a, int b, int c, int d) {
    return (uint32_t)(uint8_t)a | ((uint32_t)(uint8_t)b << 8) |
           ((uint32_t)(uint8_t)c << 16) | ((uint32_t)(uint8_t)d << 24);
}

// ---------------------------------------------------------------------------
// Kernel 1: gather + mean, emit int8 limbs (chunked over batch)
// ---------------------------------------------------------------------------
__global__ void gather_mean_split_kernel(const float* __restrict__ feat,
                                         const int* __restrict__ neigh,
                                         int b_base) {
    const int b = b_base + blockIdx.x;
    const int t = threadIdx.x;  // 0..127, owns k = 4t..4t+3

    const int* row = neigh + (size_t)b * NUM_SAMPLE;
    int ids[NUM_SAMPLE];
#pragma unroll
    for (int s = 0; s < NUM_SAMPLE; ++s) ids[s] = row[s];

    float4 acc = make_float4(0.f, 0.f, 0.f, 0.f);
#pragma unroll
    for (int s = 0; s < NUM_SAMPLE; ++s) {
        const float4 v = reinterpret_cast<const float4*>(feat + (size_t)ids[s] * FEAT_DIM)[t];
        acc.x += v.x; acc.y += v.y; acc.z += v.z; acc.w += v.w;
    }
    const float inv = 1.0f / NUM_SAMPLE;
    float x[4] = {acc.x * inv, acc.y * inv, acc.z * inv, acc.w * inv};

    int l1[4], l2[4];
#pragma unroll
    for (int j = 0; j < 4; ++j) split2(x[j], 64.f, 128.f, l1[j], l2[j]);

    reinterpret_cast<uint32_t*>(g_a1 + (size_t)b * FEAT_DIM)[t] = pack4(l1[0], l1[1], l1[2], l1[3]);
    reinterpret_cast<uint32_t*>(g_a2 + (size_t)b * FEAT_DIM)[t] = pack4(l2[0], l2[1], l2[2], l2[3]);
}

// ---------------------------------------------------------------------------
// Kernel 2: weight limbs (w*1024 -> l1 (|.|<=91); residual*128 -> l2)
// ---------------------------------------------------------------------------
__global__ void weight_split_kernel(const float* __restrict__ w) {
    const int i4 = (blockIdx.x * blockDim.x + threadIdx.x) * 4;
    const float4 v = *reinterpret_cast<const float4*>(w + i4);
    float x[4] = {v.x, v.y, v.z, v.w};
    int l1[4], l2[4];
#pragma unroll
    for (int j = 0; j < 4; ++j) split2(x[j], 1024.f, 128.f, l1[j], l2[j]);
    reinterpret_cast<uint32_t*>(g_w1)[i4 >> 2] = pack4(l1[0], l1[1], l1[2], l1[3]);
    reinterpret_cast<uint32_t*>(g_w2)[i4 >> 2] = pack4(l2[0], l2[1], l2[2], l2[3]);
}

// ---------------------------------------------------------------------------
// Kernel 3: int8 Ozaki GEMM via mma.m16n8k32.s8.s32 + fused leaky-ReLU.
// y = 2^-16*C11 + 2^-23*(C12+C21). 128x64 CTA tile, 256 thr, warp tile 32x32.
// ---------------------------------------------------------------------------
__global__ __launch_bounds__(256, 2) void gemm_s8_kernel(float* __restrict__ out,
                                                         int n_base) {
    extern __shared__ char smem[];
    const uint32_t sbase = smem_to_u32(smem);
    const int t    = threadIdx.x;
    const int lane = t & 31;
    const int w    = t >> 5;
    const int wm   = w & 3;   // m warp 0..3 (x32)
    const int wn   = w >> 2;  // n warp 0..1 (x32)
    const int m0   = blockIdx.y * BM;
    const int n0   = n_base + blockIdx.x * BN;

    // --- cp.async assignments: 1536 16B-chunks per stage, 6 per thread ---
    uint32_t soff[6];
    const char* gptr[6];
#pragma unroll
    for (int j = 0; j < 6; ++j) {
        const int i = t + j * 256;
        const int c = i & 3;
        uint32_t tb; const int8_t* garr; int grow;
        if (i < 512)       { tb = 0;                     garr = g_w1; grow = m0 + (i >> 2); }
        else if (i < 1024) { tb = TILE_W;                garr = g_w2; grow = m0 + ((i - 512) >> 2); }
        else if (i < 1280) { tb = 2 * TILE_W;            garr = g_a1; grow = n0 + ((i - 1024) >> 2); }
        else               { tb = 2 * TILE_W + TILE_A;   garr = g_a2; grow = n0 + ((i - 1280) >> 2); }
        const int lrow = (i < 1024) ? ((i & 511) >> 2) : ((i & 255) >> 2);
        soff[j] = tb + lrow * ROWB + c * 16;
        gptr[j] = (const char*)(garr + (size_t)grow * FEAT_DIM + c * 16);
    }

    // --- ldmatrix lane offsets ---
    const int sel = lane >> 3;
    const uint32_t arow = (uint32_t)(wm * 32 + (lane & 7) + (sel & 1) * 8) * ROWB + (sel >> 1) * 16;
    const uint32_t brow = (uint32_t)(wn * 32 + (lane & 7)) * ROWB + (sel & 1) * 16;

    int acc1[2][4][4], accX[2][4][4];
#pragma unroll
    for (int mt = 0; mt < 2; ++mt)
#pragma unroll
        for (int nt = 0; nt < 4; ++nt)
#pragma unroll
            for (int q = 0; q < 4; ++q) { acc1[mt][nt][q] = 0; accX[mt][nt][q] = 0; }

    // Prologue: stage chunks 0, 1
#pragma unroll
    for (int ch = 0; ch < 2; ++ch) {
        const uint32_t st = sbase + ch * STAGE_B;
#pragma unroll
        for (int j = 0; j < 6; ++j) CP_ASYNC16(st + soff[j], gptr[j] + ch * BKB);
        CP_COMMIT();
    }

    for (int ch = 0; ch < NCHUNK; ++ch) {
        if (ch < NCHUNK - 1) { CP_WAIT1(); } else { CP_WAIT0(); }
        __syncthreads();

        const uint32_t st  = sbase + (ch & 1) * STAGE_B;
        const uint32_t sW1 = st;
        const uint32_t sW2 = st + TILE_W;
        const uint32_t sA1 = st + 2 * TILE_W;
        const uint32_t sA2 = st + 2 * TILE_W + TILE_A;

#pragma unroll
        for (int ks = 0; ks < 2; ++ks) {
            uint32_t b1f[4][2], b2f[4][2];
#pragma unroll
            for (int nt = 0; nt < 4; ++nt) {
                LDSM2(b1f[nt], sA1 + brow + nt * (8 * ROWB) + ks * 32);
                LDSM2(b2f[nt], sA2 + brow + nt * (8 * ROWB) + ks * 32);
            }
#pragma unroll
            for (int mt = 0; mt < 2; ++mt) {
                uint32_t a1f[4], a2f[4];
                LDSM4(a1f, sW1 + arow + mt * (16 * ROWB) + ks * 32);
                LDSM4(a2f, sW2 + arow + mt * (16 * ROWB) + ks * 32);
#pragma unroll
                for (int nt = 0; nt < 4; ++nt) {
                    MMA_S8(acc1[mt][nt], a1f, b1f[nt][0], b1f[nt][1]);
                    MMA_S8(accX[mt][nt], a1f, b2f[nt][0], b2f[nt][1]);
                    MMA_S8(accX[mt][nt], a2f, b1f[nt][0], b1f[nt][1]);
                }
            }
        }
        __syncthreads();

        if (ch + 2 < NCHUNK) {
            const uint32_t stn = sbase + (ch & 1) * STAGE_B;
#pragma unroll
            for (int j = 0; j < 6; ++j) CP_ASYNC16(stn + soff[j], gptr[j] + (ch + 2) * BKB);
        }
        CP_COMMIT();
    }

    // --- epilogue: combine limbs, leaky ReLU, store ---
    const int lr = lane >> 2;
    const int lc = (lane & 3) * 2;
#pragma unroll
    for (int mt = 0; mt < 2; ++mt) {
#pragma unroll
        for (int nt = 0; nt < 4; ++nt) {
            float v[4];
#pragma unroll
            for (int q = 0; q < 4; ++q) {
                v[q] = __int2float_rn(acc1[mt][nt][q]) * S_MAIN +
                       __int2float_rn(accX[mt][nt][q]) * S_CROSS;
                v[q] = (v[q] >= 0.f) ? v[q] : v[q] * RRELU_SLOPE;
            }
            const int r0  = m0 + wm * 32 + mt * 16 + lr;
            const int col = n0 + wn * 32 + nt * 8 + lc;
            *reinterpret_cast<float2*>(out + (size_t)r0 * BATCH + col) = make_float2(v[0], v[1]);
            *reinterpret_cast<float2*>(out + (size_t)(r0 + 8) * BATCH + col) = make_float2(v[2], v[3]);
        }
    }
}

// ---------------------------------------------------------------------------
// Launch: fork/join pipeline. Gathers stream on the capture (legacy) stream;
// each chunk's GEMM runs on a second stream gated by an event, overlapping
// DRAM-bound gather work with tensor-bound GEMM work.
// Streams/events are host-side resources, created once on the first
// (uncaptured) correctness call — no device memory allocation.
// ---------------------------------------------------------------------------
extern "C" void kernel_launch(void* const* d_in, const int* in_sizes, int n_in,
                              void* d_out, int out_size) {
    const float* feat  = (const float*)d_in[0];
    const float* w     = (const float*)d_in[1];
    const int*   neigh = (const int*)d_in[2];
    float*       out   = (float*)d_out;

    static cudaStream_t s2 = nullptr;
    static cudaEvent_t  ev[NCHUNKS_PIPE];
    static cudaEvent_t  ev_done;
    if (s2 == nullptr) {
        cudaStreamCreateWithFlags(&s2, cudaStreamNonBlocking);
        for (int c = 0; c < NCHUNKS_PIPE; ++c)
            cudaEventCreateWithFlags(&ev[c], cudaEventDisableTiming);
        cudaEventCreateWithFlags(&ev_done, cudaEventDisableTiming);
        cudaFuncSetAttribute(gemm_s8_kernel,
                             cudaFuncAttributeMaxDynamicSharedMemorySize, SMEM_TOTAL);
    }

    // Producer side (capture stream): weight split, then 4 gather chunks.
    weight_split_kernel<<<(EMBED_DIM * FEAT_DIM) / 4 / 256, 256>>>(w);
    for (int c = 0; c < NCHUNKS_PIPE; ++c) {
        gather_mean_split_kernel<<<BCHUNK, 128>>>(feat, neigh, c * BCHUNK);
        cudaEventRecord(ev[c], 0);
    }

    // Consumer side (s2): per-chunk GEMM as soon as its gather lands.
    for (int c = 0; c < NCHUNKS_PIPE; ++c) {
        cudaStreamWaitEvent(s2, ev[c], 0);
        gemm_s8_kernel<<<dim3(BCHUNK / BN, EMBED_DIM / BM), 256, SMEM_TOTAL, s2>>>(
            out, c * BCHUNK);
    }

    // Join back into the capture stream.
    cudaEventRecord(ev_done, s2);
    cudaStreamWaitEvent(0, ev_done, 0);
}

// round 8
// speedup vs baseline: 1.3708x; 1.1990x over previous
#include <cuda_runtime.h>
#include <cstdint>

// ---------------------------------------------------------------------------
// Problem constants
// ---------------------------------------------------------------------------
#define FEAT_DIM   512
#define EMBED_DIM  256
#define BATCH      16384
#define NUM_SAMPLE 10
#define RRELU_SLOPE (11.0f / 48.0f)

// Fixed-point scales: w ~ w1*2^-10 + w2*2^-17 ; a ~ a1*2^-6 + a2*2^-13
#define S_MAIN  1.52587890625e-5f      // 2^-16
#define S_CROSS 1.1920928955078125e-7f // 2^-23

// GEMM tiling
#define BM 128
#define BN 64
#define BKB 64                   // k int8 per chunk
#define NCHUNK (FEAT_DIM / BKB)  // 8
#define ROWB 80                  // 64 data bytes + 16 pad (conflict-free ldmatrix)
#define TILE_W (128 * ROWB)      // 10240
#define TILE_A (64 * ROWB)       // 5120
#define STAGE_B (2 * TILE_W + 2 * TILE_A)  // 30720
#define NSTAGE 3
#define SMEM_TOTAL (NSTAGE * STAGE_B)      // 92160; 2 CTAs/SM (184 KB < 228 KB)

// ---------------------------------------------------------------------------
// Scratch (device globals: allocation-free rule)
// ---------------------------------------------------------------------------
__device__ int8_t g_a1[(size_t)BATCH * FEAT_DIM];      // agg limb 1
__device__ int8_t g_a2[(size_t)BATCH * FEAT_DIM];      // agg limb 2
__device__ int8_t g_w1[(size_t)EMBED_DIM * FEAT_DIM];  // weight limb 1
__device__ int8_t g_w2[(size_t)EMBED_DIM * FEAT_DIM];  // weight limb 2

// ---------------------------------------------------------------------------
// PTX helpers (sm_80-era; valid on compute_100 baseline target)
// ---------------------------------------------------------------------------
__device__ __forceinline__ uint32_t smem_to_u32(const void* p) {
    uint32_t a;
    asm("{ .reg .u64 t; cvta.to.shared.u64 t, %1; cvt.u32.u64 %0, t; }" : "=r"(a) : "l"(p));
    return a;
}

#define CP_ASYNC16(saddr, gptr) \
    asm volatile("cp.async.cg.shared.global [%0], [%1], 16;" :: "r"(saddr), "l"(gptr))
#define CP_COMMIT() asm volatile("cp.async.commit_group;")
#define CP_WAIT1()  asm volatile("cp.async.wait_group 1;")

#define LDSM4(r, addr)                                                           \
    asm volatile("ldmatrix.sync.aligned.m8n8.x4.shared.b16 {%0,%1,%2,%3}, [%4];" \
                 : "=r"((r)[0]), "=r"((r)[1]), "=r"((r)[2]), "=r"((r)[3])        \
                 : "r"(addr))

#define MMA_S8(d, a, b0_, b1_)                                                  \
    asm volatile("mma.sync.aligned.m16n8k32.row.col.s32.s8.s8.s32 "             \
                 "{%0,%1,%2,%3}, {%4,%5,%6,%7}, {%8,%9}, {%0,%1,%2,%3};"        \
                 : "+r"((d)[0]), "+r"((d)[1]), "+r"((d)[2]), "+r"((d)[3])       \
                 : "r"((a)[0]), "r"((a)[1]), "r"((a)[2]), "r"((a)[3]),          \
                   "r"(b0_), "r"(b1_))

__device__ __forceinline__ void split2(float x, float s1, float s2, int& l1, int& l2) {
    float xs = x * s1;
    xs = fminf(fmaxf(xs, -127.f), 127.f);
    const int q1 = __float2int_rn(xs);
    float r = (xs - (float)q1) * s2;
    r = fminf(fmaxf(r, -127.f), 127.f);
    l1 = q1;
    l2 = __float2int_rn(r);
}
__device__ __forceinline__ uint32_t pack4(int a, int b, int c, int d) {
    return (uint32_t)(uint8_t)a | ((uint32_t)(uint8_t)b << 8) |
           ((uint32_t)(uint8_t)c << 16) | ((uint32_t)(uint8_t)d << 24);
}

// ---------------------------------------------------------------------------
// Kernel 1: gather + mean, emit int8 limbs (round-5 winner, untouched)
// ---------------------------------------------------------------------------
__global__ void gather_mean_split_kernel(const float* __restrict__ feat,
                                         const int* __restrict__ neigh) {
    const int b = blockIdx.x;
    const int t = threadIdx.x;  // 0..127, owns k = 4t..4t+3

    const int* row = neigh + (size_t)b * NUM_SAMPLE;
    int ids[NUM_SAMPLE];
#pragma unroll
    for (int s = 0; s < NUM_SAMPLE; ++s) ids[s] = row[s];

    float4 acc = make_float4(0.f, 0.f, 0.f, 0.f);
#pragma unroll
    for (int s = 0; s < NUM_SAMPLE; ++s) {
        const float4 v = reinterpret_cast<const float4*>(feat + (size_t)ids[s] * FEAT_DIM)[t];
        acc.x += v.x; acc.y += v.y; acc.z += v.z; acc.w += v.w;
    }
    const float inv = 1.0f / NUM_SAMPLE;
    float x[4] = {acc.x * inv, acc.y * inv, acc.z * inv, acc.w * inv};

    int l1[4], l2[4];
#pragma unroll
    for (int j = 0; j < 4; ++j) split2(x[j], 64.f, 128.f, l1[j], l2[j]);

    reinterpret_cast<uint32_t*>(g_a1 + (size_t)b * FEAT_DIM)[t] = pack4(l1[0], l1[1], l1[2], l1[3]);
    reinterpret_cast<uint32_t*>(g_a2 + (size_t)b * FEAT_DIM)[t] = pack4(l2[0], l2[1], l2[2], l2[3]);
}

// ---------------------------------------------------------------------------
// Kernel 2: weight limbs (w*1024 -> l1 (|.|<=91); residual*128 -> l2)
// ---------------------------------------------------------------------------
__global__ void weight_split_kernel(const float* __restrict__ w) {
    const int i4 = (blockIdx.x * blockDim.x + threadIdx.x) * 4;
    const float4 v = *reinterpret_cast<const float4*>(w + i4);
    float x[4] = {v.x, v.y, v.z, v.w};
    int l1[4], l2[4];
#pragma unroll
    for (int j = 0; j < 4; ++j) split2(x[j], 1024.f, 128.f, l1[j], l2[j]);
    reinterpret_cast<uint32_t*>(g_w1)[i4 >> 2] = pack4(l1[0], l1[1], l1[2], l1[3]);
    reinterpret_cast<uint32_t*>(g_w2)[i4 >> 2] = pack4(l2[0], l2[1], l2[2], l2[3]);
}

// ---------------------------------------------------------------------------
// Kernel 3: int8 Ozaki GEMM, 3-stage cp.async ring, one barrier per chunk,
// refill issued BEFORE compute (write stage (ch+2)%3 != read stage ch%3).
// y = 2^-16*C11 + 2^-23*(C12+C21). 128x64 CTA, 256 thr, warp tile 32x32.
// ---------------------------------------------------------------------------
__global__ __launch_bounds__(256, 2) void gemm_s8_kernel(float* __restrict__ out) {
    extern __shared__ char smem[];
    const uint32_t sbase = smem_to_u32(smem);
    const int t    = threadIdx.x;
    const int lane = t & 31;
    const int w    = t >> 5;
    const int wm   = w & 3;   // m warp 0..3 (x32)
    const int wn   = w >> 2;  // n warp 0..1 (x32)
    const int m0   = blockIdx.y * BM;
    const int n0   = blockIdx.x * BN;

    // --- cp.async assignments: 1536 16B-chunks per stage, 6 per thread ---
    uint32_t soff[6];
    const char* gptr[6];
#pragma unroll
    for (int j = 0; j < 6; ++j) {
        const int i = t + j * 256;
        const int c = i & 3;
        uint32_t tb; const int8_t* garr; int grow;
        if (i < 512)       { tb = 0;                     garr = g_w1; grow = m0 + (i >> 2); }
        else if (i < 1024) { tb = TILE_W;                garr = g_w2; grow = m0 + ((i - 512) >> 2); }
        else if (i < 1280) { tb = 2 * TILE_W;            garr = g_a1; grow = n0 + ((i - 1024) >> 2); }
        else               { tb = 2 * TILE_W + TILE_A;   garr = g_a2; grow = n0 + ((i - 1280) >> 2); }
        const int lrow = (i < 1024) ? ((i & 511) >> 2) : ((i & 255) >> 2);
        soff[j] = tb + lrow * ROWB + c * 16;
        gptr[j] = (const char*)(garr + (size_t)grow * FEAT_DIM + c * 16);
    }

    // --- ldmatrix lane offsets ---
    const int sel = lane >> 3, li = lane & 7;
    // A: x4 = (m 0-7 k0 | m 8-15 k0 | m 0-7 k16 | m 8-15 k16)
    const uint32_t arow = (uint32_t)(wm * 32 + li + (sel & 1) * 8) * ROWB + (sel >> 1) * 16;
    // B pair: x4 = (nt_even k0 | nt_even k16 | nt_odd k0 | nt_odd k16)
    const uint32_t bpair = (uint32_t)(wn * 32 + (sel >> 1) * 8 + li) * ROWB + (sel & 1) * 16;

    int acc1[2][4][4], accX[2][4][4];
#pragma unroll
    for (int mt = 0; mt < 2; ++mt)
#pragma unroll
        for (int nt = 0; nt < 4; ++nt)
#pragma unroll
            for (int q = 0; q < 4; ++q) { acc1[mt][nt][q] = 0; accX[mt][nt][q] = 0; }

    // Prologue: chunks 0,1 -> stages 0,1
#pragma unroll
    for (int ch = 0; ch < 2; ++ch) {
        const uint32_t st = sbase + ch * STAGE_B;
#pragma unroll
        for (int j = 0; j < 6; ++j) CP_ASYNC16(st + soff[j], gptr[j] + ch * BKB);
        CP_COMMIT();
    }

    for (int ch = 0; ch < NCHUNK; ++ch) {
        CP_WAIT1();          // chunk ch landed (<=1 group pending)
        __syncthreads();     // also orders: all warps finished reading stage (ch-1)%3

        // refill BEFORE compute: stage (ch+2)%3 is not being read this chunk
        if (ch + 2 < NCHUNK) {
            const uint32_t stn = sbase + ((ch + 2) % NSTAGE) * STAGE_B;
#pragma unroll
            for (int j = 0; j < 6; ++j) CP_ASYNC16(stn + soff[j], gptr[j] + (ch + 2) * BKB);
        }
        CP_COMMIT();         // one group per iteration keeps wait-count bookkeeping exact

        const uint32_t st  = sbase + (ch % NSTAGE) * STAGE_B;
        const uint32_t sW1 = st;
        const uint32_t sW2 = st + TILE_W;
        const uint32_t sA1 = st + 2 * TILE_W;
        const uint32_t sA2 = st + 2 * TILE_W + TILE_A;

#pragma unroll
        for (int ks = 0; ks < 2; ++ks) {
            // B fragments: 2 LDSM4 per limb cover all 4 n-tiles x both k-halves
            uint32_t bf1[2][4], bf2[2][4];
#pragma unroll
            for (int ntp = 0; ntp < 2; ++ntp) {
                LDSM4(bf1[ntp], sA1 + bpair + ntp * (16 * ROWB) + ks * 32);
                LDSM4(bf2[ntp], sA2 + bpair + ntp * (16 * ROWB) + ks * 32);
            }
#pragma unroll
            for (int mt = 0; mt < 2; ++mt) {
                uint32_t a1f[4], a2f[4];
                LDSM4(a1f, sW1 + arow + mt * (16 * ROWB) + ks * 32);
                LDSM4(a2f, sW2 + arow + mt * (16 * ROWB) + ks * 32);
#pragma unroll
                for (int nt = 0; nt < 4; ++nt) {
                    const uint32_t b10 = bf1[nt >> 1][(nt & 1) * 2];
                    const uint32_t b11 = bf1[nt >> 1][(nt & 1) * 2 + 1];
                    const uint32_t b20 = bf2[nt >> 1][(nt & 1) * 2];
                    const uint32_t b21 = bf2[nt >> 1][(nt & 1) * 2 + 1];
                    MMA_S8(acc1[mt][nt], a1f, b10, b11);
                    MMA_S8(accX[mt][nt], a1f, b20, b21);
                    MMA_S8(accX[mt][nt], a2f, b10, b11);
                }
            }
        }
    }

    // --- epilogue: combine limbs, leaky ReLU, store ---
    const int lr = lane >> 2;
    const int lc = (lane & 3) * 2;
#pragma unroll
    for (int mt = 0; mt < 2; ++mt) {
#pragma unroll
        for (int nt = 0; nt < 4; ++nt) {
            float v[4];
#pragma unroll
            for (int q = 0; q < 4; ++q) {
                v[q] = __int2float_rn(acc1[mt][nt][q]) * S_MAIN +
                       __int2float_rn(accX[mt][nt][q]) * S_CROSS;
                v[q] = (v[q] >= 0.f) ? v[q] : v[q] * RRELU_SLOPE;
            }
            const int r0  = m0 + wm * 32 + mt * 16 + lr;
            const int col = n0 + wn * 32 + nt * 8 + lc;
            *reinterpret_cast<float2*>(out + (size_t)r0 * BATCH + col) = make_float2(v[0], v[1]);
            *reinterpret_cast<float2*>(out + (size_t)(r0 + 8) * BATCH + col) = make_float2(v[2], v[3]);
        }
    }
}

// ---------------------------------------------------------------------------
// Launch (single stream — overlap experiments regressed in R6/R7)
// ---------------------------------------------------------------------------
extern "C" void kernel_launch(void* const* d_in, const int* in_sizes, int n_in,
                              void* d_out, int out_size) {
    const float* feat  = (const float*)d_in[0];
    const float* w     = (const float*)d_in[1];
    const int*   neigh = (const int*)d_in[2];
    float*       out   = (float*)d_out;

    cudaFuncSetAttribute(gemm_s8_kernel,
                         cudaFuncAttributeMaxDynamicSharedMemorySize, SMEM_TOTAL);

    weight_split_kernel<<<(EMBED_DIM * FEAT_DIM) / 4 / 256, 256>>>(w);
    gather_mean_split_kernel<<<BATCH, 128>>>(feat, neigh);
    gemm_s8_kernel<<<dim3(BATCH / BN, EMBED_DIM / BM), 256, SMEM_TOTAL>>>(out);
}